// round 14
// baseline (speedup 1.0000x reference)
#include <cuda_runtime.h>
#include <cuda_bf16.h>
#include <cstdint>

#define NX     768
#define NHEAD  12
#define SEQ    2048
#define HD     64
#define BS     2
#define QKV3   (3 * NX)
#define MTOT   (BS * SEQ)      // 4096

typedef unsigned long long ull;

// ---------------- packed f32x2 helpers (attention) ----------------
#define FMA2(d, a, b, c) \
    asm("fma.rn.f32x2 %0, %1, %2, %3;" : "=l"(d) : "l"(a), "l"(b), "l"(c))
#define MUL2(d, a, b) \
    asm("mul.rn.f32x2 %0, %1, %2;" : "=l"(d) : "l"(a), "l"(b))
#define ADD2(d, a, b) \
    asm("add.rn.f32x2 %0, %1, %2;" : "=l"(d) : "l"(a), "l"(b))
#define PACK2(d, lo, hi) \
    asm("mov.b64 %0, {%1, %2};" : "=l"(d) : "f"(lo), "f"(hi))
#define UNPACK2(lo, hi, d) \
    asm("mov.b64 {%0, %1}, %2;" : "=f"(lo), "=f"(hi) : "l"(d))

// ---------------- HMMA helpers (sm_80-class, valid on compute_103) --------
__device__ __forceinline__ uint32_t smem_u32(const void* p) {
    uint32_t a;
    asm("{ .reg .u64 t; cvta.to.shared.u64 t, %1; cvt.u32.u64 %0, t; }"
        : "=r"(a) : "l"(p));
    return a;
}
#define LDSM_X4(r0, r1, r2, r3, addr) \
    asm volatile("ldmatrix.sync.aligned.m8n8.x4.shared.b16 {%0,%1,%2,%3}, [%4];" \
                 : "=r"(r0), "=r"(r1), "=r"(r2), "=r"(r3) : "r"(addr))
#define MMA16816(d, a, b0, b1) \
    asm volatile("mma.sync.aligned.m16n8k16.row.col.f32.bf16.bf16.f32 " \
                 "{%0,%1,%2,%3},{%4,%5,%6,%7},{%8,%9},{%0,%1,%2,%3};" \
                 : "+f"((d)[0]), "+f"((d)[1]), "+f"((d)[2]), "+f"((d)[3]) \
                 : "r"((a)[0]), "r"((a)[1]), "r"((a)[2]), "r"((a)[3]), \
                   "r"(b0), "r"(b1))

// ---------------- scratch (no cudaMalloc allowed) ----------------
__device__ float         g_qkv[(size_t)MTOT * QKV3];           // fp32 qkv
__device__ __nv_bfloat16 g_ah[(size_t)MTOT * NX];              // hidden hi
__device__ __nv_bfloat16 g_al[(size_t)MTOT * NX];              // hidden lo
__device__ __nv_bfloat16 g_wth[(size_t)QKV3 * NX];             // w_attn^T hi [2304,768]
__device__ __nv_bfloat16 g_wtl[(size_t)QKV3 * NX];
__device__ __nv_bfloat16 g_pth[(size_t)NX * NX];               // w_proj^T hi [768,768]
__device__ __nv_bfloat16 g_ptl[(size_t)NX * NX];
__device__ __nv_bfloat16 g_oh[(size_t)MTOT * NX];              // attn out hi
__device__ __nv_bfloat16 g_ol[(size_t)MTOT * NX];              // attn out lo

// ---------------------------------------------------------------------------
// fp32 -> bf16 hi/lo split, elementwise (vectorized by 4)
// ---------------------------------------------------------------------------
__global__ void convert_hilo(const float* __restrict__ in,
                             __nv_bfloat16* __restrict__ oh,
                             __nv_bfloat16* __restrict__ ol, int n4)
{
    int i = blockIdx.x * blockDim.x + threadIdx.x;
    if (i >= n4) return;
    float4 v = ((const float4*)in)[i];
    __nv_bfloat16 h0 = __float2bfloat16(v.x), h1 = __float2bfloat16(v.y);
    __nv_bfloat16 h2 = __float2bfloat16(v.z), h3 = __float2bfloat16(v.w);
    __nv_bfloat16 l0 = __float2bfloat16(v.x - __bfloat162float(h0));
    __nv_bfloat16 l1 = __float2bfloat16(v.y - __bfloat162float(h1));
    __nv_bfloat16 l2 = __float2bfloat16(v.z - __bfloat162float(h2));
    __nv_bfloat16 l3 = __float2bfloat16(v.w - __bfloat162float(h3));
    __nv_bfloat162 a, b;
    a.x = h0; a.y = h1; b.x = h2; b.y = h3;
    ((__nv_bfloat162*)oh)[2 * i]     = a;
    ((__nv_bfloat162*)oh)[2 * i + 1] = b;
    a.x = l0; a.y = l1; b.x = l2; b.y = l3;
    ((__nv_bfloat162*)ol)[2 * i]     = a;
    ((__nv_bfloat162*)ol)[2 * i + 1] = b;
}

// ---------------------------------------------------------------------------
// transpose + hi/lo split: in[R][C] fp32 -> oh/ol[C][R] bf16
// ---------------------------------------------------------------------------
__global__ void transpose_hilo(const float* __restrict__ in,
                               __nv_bfloat16* __restrict__ oh,
                               __nv_bfloat16* __restrict__ ol, int R, int C)
{
    __shared__ float t[32][33];
    int c0 = blockIdx.x * 32, r0 = blockIdx.y * 32;
    int tx = threadIdx.x, ty = threadIdx.y;   // 32 x 8
    #pragma unroll
    for (int i = 0; i < 4; i++)
        t[ty + i * 8][tx] = in[(size_t)(r0 + ty + i * 8) * C + c0 + tx];
    __syncthreads();
    #pragma unroll
    for (int i = 0; i < 4; i++) {
        int c = c0 + ty + i * 8;
        float v = t[tx][ty + i * 8];
        __nv_bfloat16 h = __float2bfloat16(v);
        __nv_bfloat16 l = __float2bfloat16(v - __bfloat162float(h));
        oh[(size_t)c * R + r0 + tx] = h;
        ol[(size_t)c * R + r0 + tx] = l;
    }
}

// ---------------------------------------------------------------------------
// Split-bf16 HMMA GEMM: C[M,N] = A[M,K]*B^T[N,K] + bias, fp32 out.
// A as Ah/Al [M,K] bf16; B as Bh/Bl [N,K] bf16 (pre-transposed).
// CTA tile 128x128, BK=32, 8 warps (4 along M x 2 along N), warp tile 32x64.
// 3 mma products per frag pair: AhBh + AlBh + AhBl (AlBl dropped, ~1.5e-5).
// ---------------------------------------------------------------------------
__global__ __launch_bounds__(256) void gemm_mma(
    const __nv_bfloat16* __restrict__ Ah, const __nv_bfloat16* __restrict__ Al,
    const __nv_bfloat16* __restrict__ Bh, const __nv_bfloat16* __restrict__ Bl,
    const float* __restrict__ bias, float* __restrict__ C, int N, int K)
{
    constexpr int BM = 128, BN = 128, BK = 32, ST = BK + 8;   // halves stride 40
    __shared__ __nv_bfloat16 sAh[BM * ST], sAl[BM * ST];
    __shared__ __nv_bfloat16 sBh[BN * ST], sBl[BN * ST];

    const int tid = threadIdx.x, wid = tid >> 5, lid = tid & 31;
    const int row0 = blockIdx.y * BM;
    const int col0 = blockIdx.x * BN;
    const int wm = (wid >> 1) * 32;       // warp M offset in tile
    const int wn = (wid & 1) * 64;        // warp N offset in tile

    const uint32_t bAh = smem_u32(sAh), bAl = smem_u32(sAl);
    const uint32_t bBh = smem_u32(sBh), bBl = smem_u32(sBl);

    float acc[2][8][4];
    #pragma unroll
    for (int i = 0; i < 2; i++)
        #pragma unroll
        for (int j = 0; j < 8; j++)
            #pragma unroll
            for (int v = 0; v < 4; v++) acc[i][j][v] = 0.f;

    // per-lane ldmatrix source offsets (halves)
    const int a_r  = lid & 15;            // A: row within m16
    const int a_kh = (lid >> 4) * 8;      // A: k-half
    const int b_n  = (lid & 7) + ((lid >> 4) << 3);   // B: row within n16
    const int b_kh = ((lid >> 3) & 1) * 8;            // B: k-half

    const int nchunk = K / BK;
    for (int kc = 0; kc < nchunk; kc++) {
        const int k0 = kc * BK;
        // load 4 tiles: 128 rows x 32 halves (64B) each = 512 float4; 2/thread
        #pragma unroll
        for (int i = tid; i < 512; i += 256) {
            int r = i >> 2, c = (i & 3) * 8;
            size_t ga = (size_t)(row0 + r) * K + k0 + c;
            size_t gb = (size_t)(col0 + r) * K + k0 + c;
            *(float4*)&sAh[r * ST + c] = *(const float4*)&Ah[ga];
            *(float4*)&sAl[r * ST + c] = *(const float4*)&Al[ga];
            *(float4*)&sBh[r * ST + c] = *(const float4*)&Bh[gb];
            *(float4*)&sBl[r * ST + c] = *(const float4*)&Bl[gb];
        }
        __syncthreads();

        #pragma unroll
        for (int ks = 0; ks < BK; ks += 16) {
            // A fragments (2 m16 frags for hi and lo)
            uint32_t ahf[2][4], alf[2][4];
            #pragma unroll
            for (int im = 0; im < 2; im++) {
                uint32_t off = (uint32_t)((wm + im * 16 + a_r) * ST + ks + a_kh) * 2;
                LDSM_X4(ahf[im][0], ahf[im][1], ahf[im][2], ahf[im][3], bAh + off);
                LDSM_X4(alf[im][0], alf[im][1], alf[im][2], alf[im][3], bAl + off);
            }
            uint32_t bf[4][4];
            // Bh fragments: 4 x4 loads cover n64 (regs {0,1}=n8 lo, {2,3}=n8 hi)
            #pragma unroll
            for (int g = 0; g < 4; g++) {
                uint32_t off = (uint32_t)((wn + g * 16 + b_n) * ST + ks + b_kh) * 2;
                LDSM_X4(bf[g][0], bf[g][1], bf[g][2], bf[g][3], bBh + off);
            }
            #pragma unroll
            for (int im = 0; im < 2; im++)
                #pragma unroll
                for (int g = 0; g < 4; g++) {
                    MMA16816(acc[im][2 * g],     ahf[im], bf[g][0], bf[g][1]);
                    MMA16816(acc[im][2 * g + 1], ahf[im], bf[g][2], bf[g][3]);
                    MMA16816(acc[im][2 * g],     alf[im], bf[g][0], bf[g][1]);
                    MMA16816(acc[im][2 * g + 1], alf[im], bf[g][2], bf[g][3]);
                }
            // Bl fragments (reuse regs)
            #pragma unroll
            for (int g = 0; g < 4; g++) {
                uint32_t off = (uint32_t)((wn + g * 16 + b_n) * ST + ks + b_kh) * 2;
                LDSM_X4(bf[g][0], bf[g][1], bf[g][2], bf[g][3], bBl + off);
            }
            #pragma unroll
            for (int im = 0; im < 2; im++)
                #pragma unroll
                for (int g = 0; g < 4; g++) {
                    MMA16816(acc[im][2 * g],     ahf[im], bf[g][0], bf[g][1]);
                    MMA16816(acc[im][2 * g + 1], ahf[im], bf[g][2], bf[g][3]);
                }
        }
        __syncthreads();
    }

    // epilogue: D frag thread map: r=lid>>2, c=(lid&3)*2; rows r and r+8
    const int er = lid >> 2, ec = (lid & 3) * 2;
    #pragma unroll
    for (int im = 0; im < 2; im++) {
        int mbase = row0 + wm + im * 16 + er;
        #pragma unroll
        for (int jn = 0; jn < 8; jn++) {
            int n = col0 + wn + jn * 8 + ec;
            float2 bi = *(const float2*)&bias[n];
            float2 o0 = { acc[im][jn][0] + bi.x, acc[im][jn][1] + bi.y };
            float2 o1 = { acc[im][jn][2] + bi.x, acc[im][jn][3] + bi.y };
            *(float2*)&C[(size_t)mbase * N + n]       = o0;
            *(float2*)&C[(size_t)(mbase + 8) * N + n] = o1;
        }
    }
}

// ---------------------------------------------------------------------------
// Flash attention, "raw reshape" layout, f32x2 inner loops (R11 structure,
// balanced 2-pass qb pairing). Output written as bf16 hi/lo for GEMM2.
// q[b,h,s,d] = qkv[b][u/12][(u%12)*64 + d],  u = h*2048 + s
// k: +768; v: +1536. out[b,s,h*64+d].
// ---------------------------------------------------------------------------
__global__ __launch_bounds__(128) void attn_kernel(
    const float* __restrict__ qkv, const float* __restrict__ amask,
    __nv_bfloat16* __restrict__ outh, __nv_bfloat16* __restrict__ outl)
{
    constexpr int BM = 128, BN = 32;
    constexpr int NQB = SEQ / BM;      // 16 query blocks
    const int h   = blockIdx.y;
    const int b   = blockIdx.z;
    const int tid = threadIdx.x;

    __shared__ float Ks[BN][HD];
    __shared__ float Vs[BN][HD];
    __shared__ float Ams[SEQ];

    const float* base = qkv + (size_t)b * SEQ * QKV3;

    for (int i = tid; i < SEQ; i += BM) Ams[i] = amask[b * SEQ + i];
    __syncthreads();

    #pragma unroll
    for (int pass = 0; pass < 2; pass++) {
        const int qb = pass == 0 ? (int)blockIdx.x : (NQB - 1 - (int)blockIdx.x);
        const int qidx = qb * BM + tid;

        ull q2[HD / 2];
        {
            int u = h * SEQ + qidx;
            const ulonglong2* qp =
                (const ulonglong2*)(base + (u / 12) * QKV3 + (u % 12) * HD);
            #pragma unroll
            for (int i = 0; i < HD / 4; i++) {
                ulonglong2 t = qp[i];
                q2[2 * i]     = t.x;
                q2[2 * i + 1] = t.y;
            }
        }

        ull acc2[HD / 2];
        #pragma unroll
        for (int d = 0; d < HD / 2; d++) acc2[d] = 0ull;
        float m = -3.0e38f, l = 0.f;

        const int nkb = (qb * BM + BM) / BN;   // causal
        for (int kb = 0; kb < nkb; kb++) {
            const int k0 = kb * BN;
            __syncthreads();
            #pragma unroll
            for (int i = tid; i < BN * HD / 4; i += BM) {
                int j  = i >> 4;
                int d4 = i & 15;
                int u = h * SEQ + k0 + j;
                const float* rowbase =
                    base + (u / 12) * QKV3 + (u % 12) * HD + d4 * 4;
                ((float4*)Ks)[i] = *(const float4*)(rowbase + NX);       // K
                ((float4*)Vs)[i] = *(const float4*)(rowbase + 2 * NX);   // V
            }
            __syncthreads();

            float s[BN];
            #pragma unroll
            for (int j = 0; j < BN; j++) {
                const ulonglong2* kp = (const ulonglong2*)Ks[j];
                ull c0 = 0ull, c1 = 0ull, c2 = 0ull, c3 = 0ull;
                #pragma unroll
                for (int i = 0; i < 8; i++) {
                    ulonglong2 kv0 = kp[2 * i];
                    ulonglong2 kv1 = kp[2 * i + 1];
                    FMA2(c0, q2[4 * i + 0], kv0.x, c0);
                    FMA2(c1, q2[4 * i + 1], kv0.y, c1);
                    FMA2(c2, q2[4 * i + 2], kv1.x, c2);
                    FMA2(c3, q2[4 * i + 3], kv1.y, c3);
                }
                ull t01, t23, t;
                ADD2(t01, c0, c1);
                ADD2(t23, c2, c3);
                ADD2(t, t01, t23);
                float slo, shi;
                UNPACK2(slo, shi, t);
                float sum = slo + shi;
                int k = k0 + j;
                s[j] = (k <= qidx) ? (sum * 0.125f + Ams[k])
                                   : (-10000.f + Ams[k]);
            }

            float mb = s[0];
            #pragma unroll
            for (int j = 1; j < BN; j++) mb = fmaxf(mb, s[j]);
            float mn = fmaxf(m, mb);
            float corr = __expf(m - mn);
            l *= corr;
            ull corr2;
            PACK2(corr2, corr, corr);
            #pragma unroll
            for (int d = 0; d < HD / 2; d++) MUL2(acc2[d], acc2[d], corr2);

            #pragma unroll
            for (int j = 0; j < BN; j++) {
                float p = __expf(s[j] - mn);
                l += p;
                ull pp;
                PACK2(pp, p, p);
                const ulonglong2* vp = (const ulonglong2*)Vs[j];
                #pragma unroll
                for (int i = 0; i < HD / 4; i++) {
                    ulonglong2 vv = vp[i];
                    FMA2(acc2[2 * i],     pp, vv.x, acc2[2 * i]);
                    FMA2(acc2[2 * i + 1], pp, vv.y, acc2[2 * i + 1]);
                }
            }
            m = mn;
        }

        float inv = 1.f / l;
        size_t ob = ((size_t)b * SEQ + qidx) * NX + h * HD;
        #pragma unroll
        for (int j = 0; j < HD / 2; j++) {         // acc2[j] = dims (2j, 2j+1)
            float v0, v1;
            UNPACK2(v0, v1, acc2[j]);
            v0 *= inv; v1 *= inv;
            __nv_bfloat16 h0 = __float2bfloat16(v0);
            __nv_bfloat16 h1 = __float2bfloat16(v1);
            __nv_bfloat16 l0 = __float2bfloat16(v0 - __bfloat162float(h0));
            __nv_bfloat16 l1 = __float2bfloat16(v1 - __bfloat162float(h1));
            __nv_bfloat162 hp, lp;
            hp.x = h0; hp.y = h1;
            lp.x = l0; lp.y = l1;
            *(__nv_bfloat162*)&outh[ob + 2 * j] = hp;
            *(__nv_bfloat162*)&outl[ob + 2 * j] = lp;
        }
        __syncthreads();
    }
}

// ---------------------------------------------------------------------------
extern "C" void kernel_launch(void* const* d_in, const int* in_sizes, int n_in,
                              void* d_out, int out_size)
{
    const float* hidden = (const float*)d_in[0];
    const float* amask  = (const float*)d_in[1];
    const float* w_attn = (const float*)d_in[2];
    const float* b_attn = (const float*)d_in[3];
    const float* w_proj = (const float*)d_in[4];
    const float* b_proj = (const float*)d_in[5];
    float* out = (float*)d_out;

    void* p;
    float* qkv;          cudaGetSymbolAddress(&p, g_qkv); qkv = (float*)p;
    __nv_bfloat16 *ah, *al, *wth, *wtl, *pth, *ptl, *oh, *ol;
    cudaGetSymbolAddress(&p, g_ah);  ah  = (__nv_bfloat16*)p;
    cudaGetSymbolAddress(&p, g_al);  al  = (__nv_bfloat16*)p;
    cudaGetSymbolAddress(&p, g_wth); wth = (__nv_bfloat16*)p;
    cudaGetSymbolAddress(&p, g_wtl); wtl = (__nv_bfloat16*)p;
    cudaGetSymbolAddress(&p, g_pth); pth = (__nv_bfloat16*)p;
    cudaGetSymbolAddress(&p, g_ptl); ptl = (__nv_bfloat16*)p;
    cudaGetSymbolAddress(&p, g_oh);  oh  = (__nv_bfloat16*)p;
    cudaGetSymbolAddress(&p, g_ol);  ol  = (__nv_bfloat16*)p;

    // prep: splits + weight transposes
    convert_hilo<<<(MTOT * NX / 4 + 255) / 256, 256>>>(hidden, ah, al, MTOT * NX / 4);
    transpose_hilo<<<dim3(QKV3 / 32, NX / 32), dim3(32, 8)>>>(w_attn, wth, wtl, NX, QKV3);
    transpose_hilo<<<dim3(NX / 32, NX / 32), dim3(32, 8)>>>(w_proj, pth, ptl, NX, NX);

    // QKV = hidden @ w_attn + b_attn   (HMMA split-bf16)
    gemm_mma<<<dim3(QKV3 / 128, MTOT / 128), 256>>>(ah, al, wth, wtl, b_attn, qkv, QKV3, NX);

    // attention (balanced SIMT flash), emits bf16 hi/lo
    attn_kernel<<<dim3(SEQ / 128 / 2, NHEAD, BS), 128>>>(qkv, amask, oh, ol);

    // out = attn @ w_proj + b_proj    (HMMA split-bf16)
    gemm_mma<<<dim3(NX / 128, MTOT / 128), 256>>>(oh, ol, pth, ptl, b_proj, out, NX, NX);
}

// round 16
// speedup vs baseline: 1.8112x; 1.8112x over previous
#include <cuda_runtime.h>
#include <cuda_bf16.h>
#include <cstdint>

#define NX     768
#define NHEAD  12
#define SEQ    2048
#define HD     64
#define BS     2
#define QKV3   (3 * NX)
#define MTOT   (BS * SEQ)      // 4096

typedef unsigned long long ull;

// ---------------- packed f32x2 helpers (attention) ----------------
#define FMA2(d, a, b, c) \
    asm("fma.rn.f32x2 %0, %1, %2, %3;" : "=l"(d) : "l"(a), "l"(b), "l"(c))
#define MUL2(d, a, b) \
    asm("mul.rn.f32x2 %0, %1, %2;" : "=l"(d) : "l"(a), "l"(b))
#define ADD2(d, a, b) \
    asm("add.rn.f32x2 %0, %1, %2;" : "=l"(d) : "l"(a), "l"(b))
#define PACK2(d, lo, hi) \
    asm("mov.b64 %0, {%1, %2};" : "=l"(d) : "f"(lo), "f"(hi))
#define UNPACK2(lo, hi, d) \
    asm("mov.b64 {%0, %1}, %2;" : "=f"(lo), "=f"(hi) : "l"(d))

// ---------------- HMMA helpers (sm_80-class, valid on compute_103) --------
__device__ __forceinline__ uint32_t smem_u32(const void* p) {
    uint32_t a;
    asm("{ .reg .u64 t; cvta.to.shared.u64 t, %1; cvt.u32.u64 %0, t; }"
        : "=r"(a) : "l"(p));
    return a;
}
#define LDSM_X4(r0, r1, r2, r3, addr) \
    asm volatile("ldmatrix.sync.aligned.m8n8.x4.shared.b16 {%0,%1,%2,%3}, [%4];" \
                 : "=r"(r0), "=r"(r1), "=r"(r2), "=r"(r3) : "r"(addr))
#define MMA16816(d, a, b0, b1) \
    asm volatile("mma.sync.aligned.m16n8k16.row.col.f32.bf16.bf16.f32 " \
                 "{%0,%1,%2,%3},{%4,%5,%6,%7},{%8,%9},{%0,%1,%2,%3};" \
                 : "+f"((d)[0]), "+f"((d)[1]), "+f"((d)[2]), "+f"((d)[3]) \
                 : "r"((a)[0]), "r"((a)[1]), "r"((a)[2]), "r"((a)[3]), \
                   "r"(b0), "r"(b1))

// ---------------- scratch (no cudaMalloc allowed) ----------------
__device__ float         g_qkv[(size_t)MTOT * QKV3];           // fp32 qkv
__device__ float         g_attn[(size_t)MTOT * NX];            // fp32 attn out
__device__ __nv_bfloat16 g_ah[(size_t)MTOT * NX];              // hidden hi
__device__ __nv_bfloat16 g_al[(size_t)MTOT * NX];              // hidden lo
__device__ __nv_bfloat16 g_wth[(size_t)QKV3 * NX];             // w_attn^T hi [2304,768]
__device__ __nv_bfloat16 g_wtl[(size_t)QKV3 * NX];
__device__ __nv_bfloat16 g_pth[(size_t)NX * NX];               // w_proj^T hi [768,768]
__device__ __nv_bfloat16 g_ptl[(size_t)NX * NX];
__device__ __nv_bfloat16 g_oh[(size_t)MTOT * NX];              // attn out hi
__device__ __nv_bfloat16 g_ol[(size_t)MTOT * NX];              // attn out lo

// ---------------------------------------------------------------------------
// fp32 -> bf16 hi/lo split, elementwise (vectorized by 4)
// ---------------------------------------------------------------------------
__global__ void convert_hilo(const float* __restrict__ in,
                             __nv_bfloat16* __restrict__ oh,
                             __nv_bfloat16* __restrict__ ol, int n4)
{
    int i = blockIdx.x * blockDim.x + threadIdx.x;
    if (i >= n4) return;
    float4 v = ((const float4*)in)[i];
    __nv_bfloat16 h0 = __float2bfloat16(v.x), h1 = __float2bfloat16(v.y);
    __nv_bfloat16 h2 = __float2bfloat16(v.z), h3 = __float2bfloat16(v.w);
    __nv_bfloat16 l0 = __float2bfloat16(v.x - __bfloat162float(h0));
    __nv_bfloat16 l1 = __float2bfloat16(v.y - __bfloat162float(h1));
    __nv_bfloat16 l2 = __float2bfloat16(v.z - __bfloat162float(h2));
    __nv_bfloat16 l3 = __float2bfloat16(v.w - __bfloat162float(h3));
    __nv_bfloat162 a, b;
    a.x = h0; a.y = h1; b.x = h2; b.y = h3;
    ((__nv_bfloat162*)oh)[2 * i]     = a;
    ((__nv_bfloat162*)oh)[2 * i + 1] = b;
    a.x = l0; a.y = l1; b.x = l2; b.y = l3;
    ((__nv_bfloat162*)ol)[2 * i]     = a;
    ((__nv_bfloat162*)ol)[2 * i + 1] = b;
}

// ---------------------------------------------------------------------------
// transpose + hi/lo split: in[R][C] fp32 -> oh/ol[C][R] bf16
// ---------------------------------------------------------------------------
__global__ void transpose_hilo(const float* __restrict__ in,
                               __nv_bfloat16* __restrict__ oh,
                               __nv_bfloat16* __restrict__ ol, int R, int C)
{
    __shared__ float t[32][33];
    int c0 = blockIdx.x * 32, r0 = blockIdx.y * 32;
    int tx = threadIdx.x, ty = threadIdx.y;   // 32 x 8
    #pragma unroll
    for (int i = 0; i < 4; i++)
        t[ty + i * 8][tx] = in[(size_t)(r0 + ty + i * 8) * C + c0 + tx];
    __syncthreads();
    #pragma unroll
    for (int i = 0; i < 4; i++) {
        int c = c0 + ty + i * 8;
        float v = t[tx][ty + i * 8];
        __nv_bfloat16 h = __float2bfloat16(v);
        __nv_bfloat16 l = __float2bfloat16(v - __bfloat162float(h));
        oh[(size_t)c * R + r0 + tx] = h;
        ol[(size_t)c * R + r0 + tx] = l;
    }
}

// ---------------------------------------------------------------------------
// Split-bf16 HMMA GEMM: C[M,N] = A[M,K]*B^T[N,K] + bias, fp32 out.
// CTA tile 128x128, BK=32, 8 warps (4 along M x 2 along N), warp tile 32x64.
// 3 mma products per frag pair: AhBh + AlBh + AhBl (AlBl dropped, ~1.5e-5).
// __launch_bounds__(256, 2): cap at 128 regs -> 2 CTAs/SM to hide latency.
// ---------------------------------------------------------------------------
__global__ __launch_bounds__(256, 2) void gemm_mma(
    const __nv_bfloat16* __restrict__ Ah, const __nv_bfloat16* __restrict__ Al,
    const __nv_bfloat16* __restrict__ Bh, const __nv_bfloat16* __restrict__ Bl,
    const float* __restrict__ bias, float* __restrict__ C, int N, int K)
{
    constexpr int BM = 128, BN = 128, BK = 32, ST = BK + 8;   // halves stride 40
    __shared__ __nv_bfloat16 sAh[BM * ST], sAl[BM * ST];
    __shared__ __nv_bfloat16 sBh[BN * ST], sBl[BN * ST];

    const int tid = threadIdx.x, wid = tid >> 5, lid = tid & 31;
    const int row0 = blockIdx.y * BM;
    const int col0 = blockIdx.x * BN;
    const int wm = (wid >> 1) * 32;       // warp M offset in tile
    const int wn = (wid & 1) * 64;        // warp N offset in tile

    const uint32_t bAh = smem_u32(sAh), bAl = smem_u32(sAl);
    const uint32_t bBh = smem_u32(sBh), bBl = smem_u32(sBl);

    float acc[2][8][4];
    #pragma unroll
    for (int i = 0; i < 2; i++)
        #pragma unroll
        for (int j = 0; j < 8; j++)
            #pragma unroll
            for (int v = 0; v < 4; v++) acc[i][j][v] = 0.f;

    // per-lane ldmatrix source offsets (halves)
    const int a_r  = lid & 15;            // A: row within m16
    const int a_kh = (lid >> 4) * 8;      // A: k-half
    const int b_n  = (lid & 7) + ((lid >> 4) << 3);   // B: row within n16
    const int b_kh = ((lid >> 3) & 1) * 8;            // B: k-half

    const int nchunk = K / BK;
    for (int kc = 0; kc < nchunk; kc++) {
        const int k0 = kc * BK;
        // load 4 tiles: 128 rows x 32 halves (64B) each = 512 float4; 2/thread
        #pragma unroll
        for (int i = tid; i < 512; i += 256) {
            int r = i >> 2, c = (i & 3) * 8;
            size_t ga = (size_t)(row0 + r) * K + k0 + c;
            size_t gb = (size_t)(col0 + r) * K + k0 + c;
            *(float4*)&sAh[r * ST + c] = *(const float4*)&Ah[ga];
            *(float4*)&sAl[r * ST + c] = *(const float4*)&Al[ga];
            *(float4*)&sBh[r * ST + c] = *(const float4*)&Bh[gb];
            *(float4*)&sBl[r * ST + c] = *(const float4*)&Bl[gb];
        }
        __syncthreads();

        #pragma unroll
        for (int ks = 0; ks < BK; ks += 16) {
            // A fragments (2 m16 frags for hi and lo)
            uint32_t ahf[2][4], alf[2][4];
            #pragma unroll
            for (int im = 0; im < 2; im++) {
                uint32_t off = (uint32_t)((wm + im * 16 + a_r) * ST + ks + a_kh) * 2;
                LDSM_X4(ahf[im][0], ahf[im][1], ahf[im][2], ahf[im][3], bAh + off);
                LDSM_X4(alf[im][0], alf[im][1], alf[im][2], alf[im][3], bAl + off);
            }
            uint32_t bf[4][4];
            // Bh fragments: 4 x4 loads cover n64 (regs {0,1}=n8 lo, {2,3}=n8 hi)
            #pragma unroll
            for (int g = 0; g < 4; g++) {
                uint32_t off = (uint32_t)((wn + g * 16 + b_n) * ST + ks + b_kh) * 2;
                LDSM_X4(bf[g][0], bf[g][1], bf[g][2], bf[g][3], bBh + off);
            }
            #pragma unroll
            for (int im = 0; im < 2; im++)
                #pragma unroll
                for (int g = 0; g < 4; g++) {
                    MMA16816(acc[im][2 * g],     ahf[im], bf[g][0], bf[g][1]);
                    MMA16816(acc[im][2 * g + 1], ahf[im], bf[g][2], bf[g][3]);
                    MMA16816(acc[im][2 * g],     alf[im], bf[g][0], bf[g][1]);
                    MMA16816(acc[im][2 * g + 1], alf[im], bf[g][2], bf[g][3]);
                }
            // Bl fragments (reuse regs)
            #pragma unroll
            for (int g = 0; g < 4; g++) {
                uint32_t off = (uint32_t)((wn + g * 16 + b_n) * ST + ks + b_kh) * 2;
                LDSM_X4(bf[g][0], bf[g][1], bf[g][2], bf[g][3], bBl + off);
            }
            #pragma unroll
            for (int im = 0; im < 2; im++)
                #pragma unroll
                for (int g = 0; g < 4; g++) {
                    MMA16816(acc[im][2 * g],     ahf[im], bf[g][0], bf[g][1]);
                    MMA16816(acc[im][2 * g + 1], ahf[im], bf[g][2], bf[g][3]);
                }
        }
        __syncthreads();
    }

    // epilogue: D frag thread map: r=lid>>2, c=(lid&3)*2; rows r and r+8
    const int er = lid >> 2, ec = (lid & 3) * 2;
    #pragma unroll
    for (int im = 0; im < 2; im++) {
        int mbase = row0 + wm + im * 16 + er;
        #pragma unroll
        for (int jn = 0; jn < 8; jn++) {
            int n = col0 + wn + jn * 8 + ec;
            float2 bi = *(const float2*)&bias[n];
            float2 o0 = { acc[im][jn][0] + bi.x, acc[im][jn][1] + bi.y };
            float2 o1 = { acc[im][jn][2] + bi.x, acc[im][jn][3] + bi.y };
            *(float2*)&C[(size_t)mbase * N + n]       = o0;
            *(float2*)&C[(size_t)(mbase + 8) * N + n] = o1;
        }
    }
}

// ---------------------------------------------------------------------------
// Flash attention, "raw reshape" layout, f32x2 inner loops (exact R11 kernel:
// fp32 output, no in-kernel bf16 conversion -> no register spills).
// Work balancing: CTA x does qb=x and qb=15-x (17 key-tiles each).
// q[b,h,s,d] = qkv[b][u/12][(u%12)*64 + d],  u = h*2048 + s
// k: +768; v: +1536. out[b,s,h*64+d].
// ---------------------------------------------------------------------------
__global__ __launch_bounds__(128) void attn_kernel(
    const float* __restrict__ qkv, const float* __restrict__ amask,
    float* __restrict__ attn_out)
{
    constexpr int BM = 128, BN = 32;
    constexpr int NQB = SEQ / BM;      // 16 query blocks
    const int h   = blockIdx.y;
    const int b   = blockIdx.z;
    const int tid = threadIdx.x;

    __shared__ float Ks[BN][HD];
    __shared__ float Vs[BN][HD];
    __shared__ float Ams[SEQ];

    const float* base = qkv + (size_t)b * SEQ * QKV3;

    for (int i = tid; i < SEQ; i += BM) Ams[i] = amask[b * SEQ + i];
    __syncthreads();

    #pragma unroll
    for (int pass = 0; pass < 2; pass++) {
        const int qb = pass == 0 ? (int)blockIdx.x : (NQB - 1 - (int)blockIdx.x);
        const int qidx = qb * BM + tid;

        ull q2[HD / 2];
        {
            int u = h * SEQ + qidx;
            const ulonglong2* qp =
                (const ulonglong2*)(base + (u / 12) * QKV3 + (u % 12) * HD);
            #pragma unroll
            for (int i = 0; i < HD / 4; i++) {
                ulonglong2 t = qp[i];
                q2[2 * i]     = t.x;
                q2[2 * i + 1] = t.y;
            }
        }

        ull acc2[HD / 2];
        #pragma unroll
        for (int d = 0; d < HD / 2; d++) acc2[d] = 0ull;
        float m = -3.0e38f, l = 0.f;

        const int nkb = (qb * BM + BM) / BN;   // causal
        for (int kb = 0; kb < nkb; kb++) {
            const int k0 = kb * BN;
            __syncthreads();
            #pragma unroll
            for (int i = tid; i < BN * HD / 4; i += BM) {
                int j  = i >> 4;
                int d4 = i & 15;
                int u = h * SEQ + k0 + j;
                const float* rowbase =
                    base + (u / 12) * QKV3 + (u % 12) * HD + d4 * 4;
                ((float4*)Ks)[i] = *(const float4*)(rowbase + NX);       // K
                ((float4*)Vs)[i] = *(const float4*)(rowbase + 2 * NX);   // V
            }
            __syncthreads();

            float s[BN];
            #pragma unroll
            for (int j = 0; j < BN; j++) {
                const ulonglong2* kp = (const ulonglong2*)Ks[j];
                ull c0 = 0ull, c1 = 0ull, c2 = 0ull, c3 = 0ull;
                #pragma unroll
                for (int i = 0; i < 8; i++) {
                    ulonglong2 kv0 = kp[2 * i];
                    ulonglong2 kv1 = kp[2 * i + 1];
                    FMA2(c0, q2[4 * i + 0], kv0.x, c0);
                    FMA2(c1, q2[4 * i + 1], kv0.y, c1);
                    FMA2(c2, q2[4 * i + 2], kv1.x, c2);
                    FMA2(c3, q2[4 * i + 3], kv1.y, c3);
                }
                ull t01, t23, t;
                ADD2(t01, c0, c1);
                ADD2(t23, c2, c3);
                ADD2(t, t01, t23);
                float slo, shi;
                UNPACK2(slo, shi, t);
                float sum = slo + shi;
                int k = k0 + j;
                s[j] = (k <= qidx) ? (sum * 0.125f + Ams[k])
                                   : (-10000.f + Ams[k]);
            }

            float mb = s[0];
            #pragma unroll
            for (int j = 1; j < BN; j++) mb = fmaxf(mb, s[j]);
            float mn = fmaxf(m, mb);
            float corr = __expf(m - mn);
            l *= corr;
            ull corr2;
            PACK2(corr2, corr, corr);
            #pragma unroll
            for (int d = 0; d < HD / 2; d++) MUL2(acc2[d], acc2[d], corr2);

            #pragma unroll
            for (int j = 0; j < BN; j++) {
                float p = __expf(s[j] - mn);
                l += p;
                ull pp;
                PACK2(pp, p, p);
                const ulonglong2* vp = (const ulonglong2*)Vs[j];
                #pragma unroll
                for (int i = 0; i < HD / 4; i++) {
                    ulonglong2 vv = vp[i];
                    FMA2(acc2[2 * i],     pp, vv.x, acc2[2 * i]);
                    FMA2(acc2[2 * i + 1], pp, vv.y, acc2[2 * i + 1]);
                }
            }
            m = mn;
        }

        float inv = 1.f / l;
        ull inv2;
        PACK2(inv2, inv, inv);
        ulonglong2* op =
            (ulonglong2*)(attn_out + ((size_t)b * SEQ + qidx) * NX + h * HD);
        #pragma unroll
        for (int i = 0; i < HD / 4; i++) {
            ulonglong2 t;
            MUL2(t.x, acc2[2 * i],     inv2);
            MUL2(t.y, acc2[2 * i + 1], inv2);
            op[i] = t;
        }
        __syncthreads();
    }
}

// ---------------------------------------------------------------------------
extern "C" void kernel_launch(void* const* d_in, const int* in_sizes, int n_in,
                              void* d_out, int out_size)
{
    const float* hidden = (const float*)d_in[0];
    const float* amask  = (const float*)d_in[1];
    const float* w_attn = (const float*)d_in[2];
    const float* b_attn = (const float*)d_in[3];
    const float* w_proj = (const float*)d_in[4];
    const float* b_proj = (const float*)d_in[5];
    float* out = (float*)d_out;

    void* p;
    float *qkv, *attn;
    cudaGetSymbolAddress(&p, g_qkv);  qkv  = (float*)p;
    cudaGetSymbolAddress(&p, g_attn); attn = (float*)p;
    __nv_bfloat16 *ah, *al, *wth, *wtl, *pth, *ptl, *oh, *ol;
    cudaGetSymbolAddress(&p, g_ah);  ah  = (__nv_bfloat16*)p;
    cudaGetSymbolAddress(&p, g_al);  al  = (__nv_bfloat16*)p;
    cudaGetSymbolAddress(&p, g_wth); wth = (__nv_bfloat16*)p;
    cudaGetSymbolAddress(&p, g_wtl); wtl = (__nv_bfloat16*)p;
    cudaGetSymbolAddress(&p, g_pth); pth = (__nv_bfloat16*)p;
    cudaGetSymbolAddress(&p, g_ptl); ptl = (__nv_bfloat16*)p;
    cudaGetSymbolAddress(&p, g_oh);  oh  = (__nv_bfloat16*)p;
    cudaGetSymbolAddress(&p, g_ol);  ol  = (__nv_bfloat16*)p;

    // prep: splits + weight transposes
    convert_hilo<<<(MTOT * NX / 4 + 255) / 256, 256>>>(hidden, ah, al, MTOT * NX / 4);
    transpose_hilo<<<dim3(QKV3 / 32, NX / 32), dim3(32, 8)>>>(w_attn, wth, wtl, NX, QKV3);
    transpose_hilo<<<dim3(NX / 32, NX / 32), dim3(32, 8)>>>(w_proj, pth, ptl, NX, NX);

    // QKV = hidden @ w_attn + b_attn   (HMMA split-bf16)
    gemm_mma<<<dim3(QKV3 / 128, MTOT / 128), 256>>>(ah, al, wth, wtl, b_attn, qkv, QKV3, NX);

    // attention (balanced SIMT flash), fp32 out
    attn_kernel<<<dim3(SEQ / 128 / 2, NHEAD, BS), 128>>>(qkv, amask, attn);

    // split attn output to bf16 hi/lo, then out = attn @ w_proj + b_proj
    convert_hilo<<<(MTOT * NX / 4 + 255) / 256, 256>>>(attn, oh, ol, MTOT * NX / 4);
    gemm_mma<<<dim3(NX / 128, MTOT / 128), 256>>>(oh, ol, pth, ptl, b_proj, out, NX, NX);
}